// round 15
// baseline (speedup 1.0000x reference)
#include <cuda_runtime.h>
#include <math.h>

#define BB 64
#define PP 24564
#define CC 81
#define TT 24
#define THRESH_F 0.5f
#define FULLMASK 0xffffffffu

// fused kernel geometry: 740 blocks x 96 threads (2 conf warps + 1 match warp)
#define NBLK 740
#define CW_BUFS 2
#define CW_ROWS 32
#define CW_F4 ((CW_ROWS * CC) / 4)     // 648 float4 per tile
#define CW_TILEF (CW_ROWS * CC)        // 2592 floats
#define CONF_TILES ((BB * PP) / CW_ROWS)      // 49128
#define NCWARPS (NBLK * 2)             // 1480 conf warps
#define NMWARPS NBLK                   // 740 match warps (warp 2 of each block)
#define MCH_PER_B 768                  // 32-prior chunks per batch
#define MCHUNKS (MCH_PER_B * BB)       // 49152
#define SMEM_CONF_F (2 * CW_BUFS * CW_TILEF)      // 10368 floats
#define FUSED_SMEM ((SMEM_CONF_F + 256) * 4)      // 42496 B -> 5 blocks/SM

// ---------------------------------------------------------------------------
// Scratch (device globals — no allocation allowed)
// ---------------------------------------------------------------------------
__device__ unsigned long long g_bp[BB * TT];        // packed (iou_bits<<32)|~p
__device__ unsigned char g_match[(size_t)BB * PP];  // 0xFF = negative, else positive
__device__ float g_closs[(size_t)BB * PP];          // lse - c0 raw (ALL rows)
__device__ unsigned int g_plist[(size_t)BB * PP];   // packed (row<<8)|lbl
__device__ int g_pcount;
__device__ double g_loc, g_poscls, g_negcls;
__device__ int g_numpos[BB];
__device__ int g_nsel;

__device__ __forceinline__ void cp_async16(unsigned int smem_dst, const void* gsrc) {
    asm volatile("cp.async.cg.shared.global [%0], [%1], 16;"
                 :: "r"(smem_dst), "l"(gsrc));
}

// ---------------------------------------------------------------------------
// Kernel 0: zero-init scratch
// ---------------------------------------------------------------------------
__global__ void k_init() {
    int i = blockIdx.x * blockDim.x + threadIdx.x;
    if (i < BB * TT) g_bp[i] = 0ULL;
    if (i < BB) g_numpos[i] = 0;
    if (i == 0) { g_loc = 0.0; g_poscls = 0.0; g_negcls = 0.0; g_nsel = 0; g_pcount = 0; }
}

// ---------------------------------------------------------------------------
// Kernel 1 (FUSED, 2 conf : 1 match): conf warps stream conf_pred (memory-
// bound critical path); the single match warp per block does 66 chunks —
// enough parallelism to finish inside conf's envelope, half the concurrent
// contention of the 2:2 split.
// ---------------------------------------------------------------------------
__global__ void __launch_bounds__(96) k_fused(const float* __restrict__ conf_pred,
                                              const float* __restrict__ loc_pred,
                                              const float* __restrict__ targets,
                                              const float* __restrict__ anchors) {
    extern __shared__ float smem[];
    const int lane = threadIdx.x & 31;
    const int w = threadIdx.x >> 5;

    if (w < 2) {
        // ================= CONF PATH =========================================
        const int gw = blockIdx.x * 2 + w;               // 0..1479
        float* wbase = smem + w * (CW_BUFS * CW_TILEF);
        unsigned int sb0 = (unsigned int)__cvta_generic_to_shared(wbase);

        int tile = gw;
        {
            const float4* src = (const float4*)(conf_pred + (size_t)tile * CW_TILEF);
            #pragma unroll
            for (int i = lane; i < CW_F4; i += 32)
                cp_async16(sb0 + i * 16, src + i);
            asm volatile("cp.async.commit_group;");
        }
        int buf = 0;
        for (; tile < CONF_TILES; tile += NCWARPS) {
            const int nt = tile + NCWARPS;
            if (nt < CONF_TILES) {
                const float4* src = (const float4*)(conf_pred + (size_t)nt * CW_TILEF);
                unsigned int dst = sb0 + (buf ^ 1) * (CW_TILEF * 4);
                #pragma unroll
                for (int i = lane; i < CW_F4; i += 32)
                    cp_async16(dst + i * 16, src + i);
            }
            asm volatile("cp.async.commit_group;");
            asm volatile("cp.async.wait_group 1;");
            __syncwarp();

            const float* rp = wbase + buf * CW_TILEF + lane * CC;
            float a0 = 0.f, a1 = 0.f, a2 = 0.f;
            #pragma unroll 9
            for (int e = 0; e < CC; e += 3) {
                a0 += __expf(rp[e]);
                a1 += __expf(rp[e + 1]);
                a2 += __expf(rp[e + 2]);
            }
            const float lse = __logf((a0 + a1) + a2);
            g_closs[(size_t)tile * CW_ROWS + lane] = lse - rp[0];   // raw, ALL rows

            buf ^= 1;
            __syncwarp();
        }
    } else {
        // ================= MATCH PATH (740 warps, ~66 chunks each) ===========
        const int gw2 = blockIdx.x;                      // 0..739
        float* tc = smem + SMEM_CONF_F;                  // warp-private truth cache
        float* t_box = tc;            // [24][4] xyxy
        float* t_ta  = tc + 96;       // [24]
        float* t_cwh = tc + 120;      // [24][4]
        float* t_lbl = tc + 216;      // [24]

        const int c0 = (int)(((long long)gw2 * MCHUNKS) / NMWARPS);
        const int c1 = (int)(((long long)(gw2 + 1) * MCHUNKS) / NMWARPS);

        unsigned int cur[TT];         // warp-uniform running max (iou bits)
        int bcur = -1;

        for (int c = c0; c < c1; c++) {
            const int b = c / MCH_PER_B;
            const int p = (c - b * MCH_PER_B) * 32 + lane;
            if (b != bcur) {
                __syncwarp();
                if (lane < TT) {
                    const float* tr = targets + ((size_t)b * TT + lane) * 5;
                    float x0 = tr[0], y0 = tr[1], x1 = tr[2], y1 = tr[3];
                    t_box[lane * 4 + 0] = x0; t_box[lane * 4 + 1] = y0;
                    t_box[lane * 4 + 2] = x1; t_box[lane * 4 + 3] = y1;
                    t_ta[lane] = (x1 - x0) * (y1 - y0);
                    t_cwh[lane * 4 + 0] = (x0 + x1) * 0.5f;
                    t_cwh[lane * 4 + 1] = (y0 + y1) * 0.5f;
                    t_cwh[lane * 4 + 2] = x1 - x0;
                    t_cwh[lane * 4 + 3] = y1 - y0;
                    t_lbl[lane] = tr[4];
                }
                __syncwarp();
                #pragma unroll
                for (int t = 0; t < TT; t++) cur[t] = 0u;
                bcur = b;
            }

            const bool valid = (p < PP);
            float4 a = make_float4(0.f, 0.f, 1.f, 1.f);
            if (valid) a = ((const float4*)anchors)[p];
            const float ax0 = a.x - a.z * 0.5f, ay0 = a.y - a.w * 0.5f;
            const float ax1 = a.x + a.z * 0.5f, ay1 = a.y + a.w * 0.5f;
            const float aarea = (ax1 - ax0) * (ay1 - ay0);

            float best = -1.0f; int bt = 0;
            #pragma unroll
            for (int t = 0; t < TT; t++) {
                float lx = fmaxf(t_box[t * 4 + 0], ax0), ly = fmaxf(t_box[t * 4 + 1], ay0);
                float rx = fminf(t_box[t * 4 + 2], ax1), ry = fminf(t_box[t * 4 + 3], ay1);
                float ww = fmaxf(rx - lx, 0.f), hh = fmaxf(ry - ly, 0.f);
                float inter = ww * hh;
                float iou = __fdividef(inter, t_ta[t] + aarea - inter);
                if (iou > best) { best = iou; bt = t; }   // strict >: first index
                unsigned int ib = valid ? __float_as_uint(iou) : 0u;
                if (__any_sync(FULLMASK, ib > cur[t])) {
                    unsigned long long pk = valid
                        ? (((unsigned long long)ib << 32)
                           | (unsigned long long)(unsigned int)(~p))
                        : 0ULL;
                    #pragma unroll
                    for (int o = 16; o; o >>= 1) {
                        unsigned long long q = __shfl_xor_sync(FULLMASK, pk, o);
                        if (q > pk) pk = q;
                    }
                    cur[t] = (unsigned int)(pk >> 32);
                    if (lane == 0) atomicMax(&g_bp[b * TT + t], pk);
                }
            }

            const bool pos = valid && (best > THRESH_F);
            const unsigned int pm = __ballot_sync(FULLMASK, pos);
            const unsigned int row = (unsigned int)(b * PP + p);
            float lt = 0.f; int lbl = 0;
            if (pos) {
                lbl = (int)t_lbl[bt];
                float4 lp = ((const float4*)loc_pred)[row];
                float e0 = (t_cwh[bt * 4 + 0] - a.x) / a.z;
                float e1 = (t_cwh[bt * 4 + 1] - a.y) / a.w;
                float e2 = __logf(t_cwh[bt * 4 + 2]) - __logf(a.z);
                float e3 = __logf(t_cwh[bt * 4 + 3]) - __logf(a.w);
                float d, ad;
                d = lp.x - e0; ad = fabsf(d); lt += (ad < 1.f) ? 0.5f * d * d : ad - 0.5f;
                d = lp.y - e1; ad = fabsf(d); lt += (ad < 1.f) ? 0.5f * d * d : ad - 0.5f;
                d = lp.z - e2; ad = fabsf(d); lt += (ad < 1.f) ? 0.5f * d * d : ad - 0.5f;
                d = lp.w - e3; ad = fabsf(d); lt += (ad < 1.f) ? 0.5f * d * d : ad - 0.5f;
            }
            if (pm) {   // warp-aggregated positive bookkeeping
                const int n = __popc(pm);
                const int leader = __ffs(pm) - 1;
                unsigned int base = 0;
                if (lane == leader) base = (unsigned int)atomicAdd(&g_pcount, n);
                base = __shfl_sync(FULLMASK, base, leader);
                if (pos) {
                    int off = __popc(pm & ((1u << lane) - 1u));
                    g_plist[base + off] = (row << 8) | (unsigned int)lbl;
                }
                double dlt = (double)lt;
                #pragma unroll
                for (int o = 16; o; o >>= 1) dlt += __shfl_xor_sync(FULLMASK, dlt, o);
                if (lane == leader) {
                    atomicAdd(&g_loc, dlt);
                    atomicAdd(&g_numpos[b], n);
                }
            }
            if (valid) g_match[row] = pos ? (unsigned char)bt : (unsigned char)0xFF;
        }
    }
}

// ---------------------------------------------------------------------------
// Kernel 2: scatter fixup — row p = best_prior[b][t] becomes positive with
// truth t (last t wins among duplicates) iff its best overlap <= 0.5.
// Marks g_match so k_select's positive mask covers these rows.
// ---------------------------------------------------------------------------
__global__ void k_fix(const float* __restrict__ loc_pred,
                      const float* __restrict__ targets,
                      const float* __restrict__ anchors) {
    const int b = blockIdx.x;
    const int t = threadIdx.x;
    if (t >= TT) return;
    unsigned long long pk = g_bp[b * TT + t];
    const int p = (int)(~(unsigned int)(pk & 0xFFFFFFFFull));
    unsigned int peers = __match_any_sync(0x00FFFFFFu, p);
    if (t != 31 - __clz(peers)) return;          // last t wins
    const unsigned int row = (unsigned int)(b * PP + p);
    if (g_match[row] != 0xFF) return;            // bt-match already positive
    g_match[row] = (unsigned char)t;             // mark positive for k_select mask

    const float* tr = targets + ((size_t)b * TT + t) * 5;
    float x0 = tr[0], y0 = tr[1], x1 = tr[2], y1 = tr[3];
    int lbl = (int)tr[4];
    int idx = atomicAdd(&g_pcount, 1);
    g_plist[idx] = (row << 8) | (unsigned int)lbl;

    float4 a = ((const float4*)anchors)[p];
    float4 lp = ((const float4*)loc_pred)[row];
    float e0 = ((x0 + x1) * 0.5f - a.x) / a.z;
    float e1 = ((y0 + y1) * 0.5f - a.y) / a.w;
    float e2 = __logf(x1 - x0) - __logf(a.z);
    float e3 = __logf(y1 - y0) - __logf(a.w);
    float d, ad, lt = 0.f;
    d = lp.x - e0; ad = fabsf(d); lt += (ad < 1.f) ? 0.5f * d * d : ad - 0.5f;
    d = lp.y - e1; ad = fabsf(d); lt += (ad < 1.f) ? 0.5f * d * d : ad - 0.5f;
    d = lp.z - e2; ad = fabsf(d); lt += (ad < 1.f) ? 0.5f * d * d : ad - 0.5f;
    d = lp.w - e3; ad = fabsf(d); lt += (ad < 1.f) ? 0.5f * d * d : ad - 0.5f;
    atomicAdd(&g_loc, (double)lt);
    atomicAdd(&g_numpos[b], 1);
}

// ---------------------------------------------------------------------------
// Kernel 3: per-batch exact K-th-largest; register-cached values with the
// positive mask applied at load (g_match != 0xFF -> 0); warp-aggregated
// histogram atomics. (Launched 4th so the profiler captures it this round.)
// ---------------------------------------------------------------------------
__global__ void __launch_bounds__(1024) k_select() {
    __shared__ int hist[256];
    __shared__ unsigned int s_sel;
    __shared__ int s_r;
    __shared__ double s_sum;
    __shared__ int s_cnt;

    const int b = blockIdx.x;
    const int tid = threadIdx.x;
    const int lane = tid & 31;
    const int np = g_numpos[b];
    long long Kl = 3LL * np;
    if (Kl > PP - 1) Kl = PP - 1;
    const int K = (int)Kl;
    if (K <= 0) {
        if (tid == 0) atomicAdd(&g_nsel, np);
        return;
    }
    const float* cl = g_closs + (size_t)b * PP;
    const unsigned char* gm = g_match + (size_t)b * PP;

    // Padding/positives -> 0u (=0.0f): bin 0; selection never descends there
    // (K-th largest closs > 0).
    unsigned int v[24];
    #pragma unroll
    for (int i = 0; i < 24; i++) {
        int idx = tid + i * 1024;
        bool neg = (idx < PP) && (gm[idx] == 0xFF);
        v[i] = neg ? __float_as_uint(cl[idx]) : 0u;
    }

    unsigned int prefix = 0, pmask = 0;
    int r = K;
    #pragma unroll
    for (int shift = 24; shift >= 0; shift -= 8) {
        if (tid < 256) hist[tid] = 0;
        __syncthreads();
        #pragma unroll
        for (int i = 0; i < 24; i++) {
            unsigned int u = v[i];
            bool act = ((u & pmask) == prefix);
            unsigned int bal = __ballot_sync(FULLMASK, act);
            if (act) {
                unsigned int bin = (u >> shift) & 255u;
                unsigned int peers = __match_any_sync(bal, bin);
                if (lane == __ffs(peers) - 1)
                    atomicAdd(&hist[bin], __popc(peers));
            }
        }
        __syncthreads();
        if (tid == 0) {
            int cum = 0; unsigned int sel = 0;
            for (int bin = 255; bin >= 0; bin--) {
                int nc = cum + hist[bin];
                if (nc >= r) { sel = (unsigned int)bin; break; }
                cum = nc;
            }
            s_sel = sel; s_r = r - cum;
        }
        __syncthreads();
        prefix |= s_sel << shift;
        pmask |= 0xFFu << shift;
        r = s_r;
    }
    const float theta = __uint_as_float(prefix);   // exact K-th largest

    if (tid == 0) { s_sum = 0.0; s_cnt = 0; }
    __syncthreads();
    double sum = 0.0; int cnt = 0;
    #pragma unroll
    for (int i = 0; i < 24; i++) {
        float f = __uint_as_float(v[i]);
        if (f > theta) { sum += (double)f; cnt++; }
    }
    #pragma unroll
    for (int o = 16; o; o >>= 1) {
        sum += __shfl_xor_sync(FULLMASK, sum, o);
        cnt += __shfl_xor_sync(FULLMASK, cnt, o);
    }
    if (lane == 0) { atomicAdd(&s_sum, sum); atomicAdd(&s_cnt, cnt); }
    __syncthreads();
    if (tid == 0) {
        double negsum = s_sum + (double)(K - s_cnt) * (double)theta;
        atomicAdd(&g_negcls, negsum);
        atomicAdd(&g_nsel, np + K);
    }
}

// ---------------------------------------------------------------------------
// Kernel 4: positive gather (independent of k_select; runs after it).
//   poscls += closs_raw[row] + conf[row][0] - conf[row][lbl]   (= lse - conf[lbl])
// ---------------------------------------------------------------------------
__global__ void k_zero(const float* __restrict__ conf_pred) {
    const int n = g_pcount;
    const int lane = threadIdx.x & 31;
    double acc = 0.0;
    for (int i = blockIdx.x * blockDim.x + threadIdx.x; i < n;
         i += gridDim.x * blockDim.x) {
        unsigned int e = g_plist[i];
        size_t row = (size_t)(e >> 8);
        int lbl = (int)(e & 255u);
        const float* cp = conf_pred + row * CC;
        acc += (double)(g_closs[row] + __ldg(cp) - __ldg(cp + lbl));
    }
    #pragma unroll
    for (int o = 16; o; o >>= 1) acc += __shfl_xor_sync(FULLMASK, acc, o);
    if (lane == 0 && acc != 0.0) atomicAdd(&g_poscls, acc);
}

// ---------------------------------------------------------------------------
// Kernel 5: combine (non-selected rows each contribute exactly log C).
// ---------------------------------------------------------------------------
__global__ void k_final(float* out) {
    const int t = threadIdx.x;           // 64 threads
    int np = (t < BB) ? g_numpos[t] : 0;
    #pragma unroll
    for (int o = 16; o; o >>= 1) np += __shfl_xor_sync(FULLMASK, np, o);
    __shared__ int s_np[2];
    if ((t & 31) == 0) s_np[t >> 5] = np;
    __syncthreads();
    if (t == 0) {
        double N = (double)(s_np[0] + s_np[1]);
        double cls = g_poscls + g_negcls +
                     (double)((long long)BB * PP - (long long)g_nsel) * log((double)CC);
        out[0] = (float)(g_loc / N);
        out[1] = (float)(cls / N);
    }
}

// ---------------------------------------------------------------------------
// Launch
// ---------------------------------------------------------------------------
extern "C" void kernel_launch(void* const* d_in, const int* in_sizes, int n_in,
                              void* d_out, int out_size) {
    const float *loc = nullptr, *conf = nullptr, *tgt = nullptr, *anc = nullptr;
    for (int i = 0; i < n_in; i++) {
        long long s = in_sizes[i];
        if (s == (long long)BB * PP * 4)       loc  = (const float*)d_in[i];
        else if (s == (long long)BB * PP * CC) conf = (const float*)d_in[i];
        else if (s == (long long)BB * TT * 5)  tgt  = (const float*)d_in[i];
        else if (s == (long long)PP * 4)       anc  = (const float*)d_in[i];
    }
    float* out = (float*)d_out;

    k_init<<<(BB * TT + 255) / 256, 256>>>();          // 1
    k_fused<<<NBLK, 96, FUSED_SMEM>>>(conf, loc, tgt, anc);  // 2
    k_fix<<<BB, 32>>>(loc, tgt, anc);                  // 3
    k_select<<<BB, 1024>>>();                          // 4  <- profiled
    k_zero<<<592, 128>>>(conf);                        // 5 (independent of select)
    k_final<<<1, 64>>>(out);                           // 6
}

// round 16
// speedup vs baseline: 1.4872x; 1.4872x over previous
#include <cuda_runtime.h>
#include <math.h>

#define BB 64
#define PP 24564
#define CC 81
#define TT 24
#define THRESH_F 0.5f
#define FULLMASK 0xffffffffu

// fused kernel geometry: 740 blocks x 128 threads (2 conf + 2 match warps)
#define NBLK 740
#define CW_BUFS 2
#define CW_ROWS 32
#define CW_F4 ((CW_ROWS * CC) / 4)     // 648 float4 per tile
#define CW_TILEF (CW_ROWS * CC)        // 2592 floats
#define CONF_TILES ((BB * PP) / CW_ROWS)      // 49128
#define NCWARPS (NBLK * 2)             // 1480 conf warps
#define NMWARPS (NBLK * 2)             // 1480 match warps
#define MCH_PER_B 768                  // 32-prior chunks per batch
#define MCHUNKS (MCH_PER_B * BB)       // 49152
#define SMEM_CONF_F (2 * CW_BUFS * CW_TILEF)      // 10368 floats
#define FUSED_SMEM ((SMEM_CONF_F + 2 * 256) * 4)  // 43520 B -> 5 blocks/SM

// ---------------------------------------------------------------------------
// Scratch (device globals — no allocation allowed)
// ---------------------------------------------------------------------------
__device__ unsigned long long g_bp[BB * TT];        // packed (iou_bits<<32)|~p
__device__ unsigned char g_match[(size_t)BB * PP];  // 0xFF = negative, else positive
__device__ float g_closs[(size_t)BB * PP];          // lse - c0 raw (ALL rows)
__device__ unsigned int g_plist[(size_t)BB * PP];   // packed (row<<8)|lbl
__device__ int g_pcount;
__device__ double g_loc, g_poscls, g_negcls;
__device__ int g_numpos[BB];
__device__ int g_nsel;

__device__ __forceinline__ void cp_async16(unsigned int smem_dst, const void* gsrc) {
    asm volatile("cp.async.cg.shared.global [%0], [%1], 16;"
                 :: "r"(smem_dst), "l"(gsrc));
}

// ---------------------------------------------------------------------------
// Kernel 0: zero-init scratch
// ---------------------------------------------------------------------------
__global__ void k_init() {
    int i = blockIdx.x * blockDim.x + threadIdx.x;
    if (i < BB * TT) g_bp[i] = 0ULL;
    if (i < BB) g_numpos[i] = 0;
    if (i == 0) { g_loc = 0.0; g_poscls = 0.0; g_negcls = 0.0; g_nsel = 0; g_pcount = 0; }
}

// ---------------------------------------------------------------------------
// Kernel 1 (FUSED, 2 conf : 2 match — the measured-best R13 balance).
// ---------------------------------------------------------------------------
__global__ void __launch_bounds__(128) k_fused(const float* __restrict__ conf_pred,
                                               const float* __restrict__ loc_pred,
                                               const float* __restrict__ targets,
                                               const float* __restrict__ anchors) {
    extern __shared__ float smem[];
    const int lane = threadIdx.x & 31;
    const int w = threadIdx.x >> 5;

    if (w < 2) {
        // ================= CONF PATH =========================================
        const int gw = blockIdx.x * 2 + w;               // 0..1479
        float* wbase = smem + w * (CW_BUFS * CW_TILEF);
        unsigned int sb0 = (unsigned int)__cvta_generic_to_shared(wbase);

        int tile = gw;
        {
            const float4* src = (const float4*)(conf_pred + (size_t)tile * CW_TILEF);
            #pragma unroll
            for (int i = lane; i < CW_F4; i += 32)
                cp_async16(sb0 + i * 16, src + i);
            asm volatile("cp.async.commit_group;");
        }
        int buf = 0;
        for (; tile < CONF_TILES; tile += NCWARPS) {
            const int nt = tile + NCWARPS;
            if (nt < CONF_TILES) {
                const float4* src = (const float4*)(conf_pred + (size_t)nt * CW_TILEF);
                unsigned int dst = sb0 + (buf ^ 1) * (CW_TILEF * 4);
                #pragma unroll
                for (int i = lane; i < CW_F4; i += 32)
                    cp_async16(dst + i * 16, src + i);
            }
            asm volatile("cp.async.commit_group;");
            asm volatile("cp.async.wait_group 1;");
            __syncwarp();

            const float* rp = wbase + buf * CW_TILEF + lane * CC;
            float a0 = 0.f, a1 = 0.f, a2 = 0.f;
            #pragma unroll 9
            for (int e = 0; e < CC; e += 3) {
                a0 += __expf(rp[e]);
                a1 += __expf(rp[e + 1]);
                a2 += __expf(rp[e + 2]);
            }
            const float lse = __logf((a0 + a1) + a2);
            g_closs[(size_t)tile * CW_ROWS + lane] = lse - rp[0];   // raw, ALL rows

            buf ^= 1;
            __syncwarp();
        }
    } else {
        // ================= MATCH PATH (1480 warps, ~33 chunks each) ==========
        const int gw2 = blockIdx.x * 2 + (w - 2);        // 0..1479
        float* tc = smem + SMEM_CONF_F + (w - 2) * 256;  // warp-private truth cache
        float* t_box = tc;            // [24][4] xyxy
        float* t_ta  = tc + 96;       // [24]
        float* t_cwh = tc + 120;      // [24][4]
        float* t_lbl = tc + 216;      // [24]

        const int c0 = (int)(((long long)gw2 * MCHUNKS) / NMWARPS);
        const int c1 = (int)(((long long)(gw2 + 1) * MCHUNKS) / NMWARPS);

        unsigned int cur[TT];         // warp-uniform running max (iou bits)
        int bcur = -1;

        for (int c = c0; c < c1; c++) {
            const int b = c / MCH_PER_B;
            const int p = (c - b * MCH_PER_B) * 32 + lane;
            if (b != bcur) {
                __syncwarp();
                if (lane < TT) {
                    const float* tr = targets + ((size_t)b * TT + lane) * 5;
                    float x0 = tr[0], y0 = tr[1], x1 = tr[2], y1 = tr[3];
                    t_box[lane * 4 + 0] = x0; t_box[lane * 4 + 1] = y0;
                    t_box[lane * 4 + 2] = x1; t_box[lane * 4 + 3] = y1;
                    t_ta[lane] = (x1 - x0) * (y1 - y0);
                    t_cwh[lane * 4 + 0] = (x0 + x1) * 0.5f;
                    t_cwh[lane * 4 + 1] = (y0 + y1) * 0.5f;
                    t_cwh[lane * 4 + 2] = x1 - x0;
                    t_cwh[lane * 4 + 3] = y1 - y0;
                    t_lbl[lane] = tr[4];
                }
                __syncwarp();
                #pragma unroll
                for (int t = 0; t < TT; t++) cur[t] = 0u;
                bcur = b;
            }

            const bool valid = (p < PP);
            float4 a = make_float4(0.f, 0.f, 1.f, 1.f);
            if (valid) a = ((const float4*)anchors)[p];
            const float ax0 = a.x - a.z * 0.5f, ay0 = a.y - a.w * 0.5f;
            const float ax1 = a.x + a.z * 0.5f, ay1 = a.y + a.w * 0.5f;
            const float aarea = (ax1 - ax0) * (ay1 - ay0);

            float best = -1.0f; int bt = 0;
            #pragma unroll
            for (int t = 0; t < TT; t++) {
                float lx = fmaxf(t_box[t * 4 + 0], ax0), ly = fmaxf(t_box[t * 4 + 1], ay0);
                float rx = fminf(t_box[t * 4 + 2], ax1), ry = fminf(t_box[t * 4 + 3], ay1);
                float ww = fmaxf(rx - lx, 0.f), hh = fmaxf(ry - ly, 0.f);
                float inter = ww * hh;
                float iou = __fdividef(inter, t_ta[t] + aarea - inter);
                if (iou > best) { best = iou; bt = t; }   // strict >: first index
                unsigned int ib = valid ? __float_as_uint(iou) : 0u;
                if (__any_sync(FULLMASK, ib > cur[t])) {
                    unsigned long long pk = valid
                        ? (((unsigned long long)ib << 32)
                           | (unsigned long long)(unsigned int)(~p))
                        : 0ULL;
                    #pragma unroll
                    for (int o = 16; o; o >>= 1) {
                        unsigned long long q = __shfl_xor_sync(FULLMASK, pk, o);
                        if (q > pk) pk = q;
                    }
                    cur[t] = (unsigned int)(pk >> 32);
                    if (lane == 0) atomicMax(&g_bp[b * TT + t], pk);
                }
            }

            const bool pos = valid && (best > THRESH_F);
            const unsigned int pm = __ballot_sync(FULLMASK, pos);
            const unsigned int row = (unsigned int)(b * PP + p);
            float lt = 0.f; int lbl = 0;
            if (pos) {
                lbl = (int)t_lbl[bt];
                float4 lp = ((const float4*)loc_pred)[row];
                float e0 = (t_cwh[bt * 4 + 0] - a.x) / a.z;
                float e1 = (t_cwh[bt * 4 + 1] - a.y) / a.w;
                float e2 = __logf(t_cwh[bt * 4 + 2]) - __logf(a.z);
                float e3 = __logf(t_cwh[bt * 4 + 3]) - __logf(a.w);
                float d, ad;
                d = lp.x - e0; ad = fabsf(d); lt += (ad < 1.f) ? 0.5f * d * d : ad - 0.5f;
                d = lp.y - e1; ad = fabsf(d); lt += (ad < 1.f) ? 0.5f * d * d : ad - 0.5f;
                d = lp.z - e2; ad = fabsf(d); lt += (ad < 1.f) ? 0.5f * d * d : ad - 0.5f;
                d = lp.w - e3; ad = fabsf(d); lt += (ad < 1.f) ? 0.5f * d * d : ad - 0.5f;
            }
            if (pm) {   // warp-aggregated positive bookkeeping
                const int n = __popc(pm);
                const int leader = __ffs(pm) - 1;
                unsigned int base = 0;
                if (lane == leader) base = (unsigned int)atomicAdd(&g_pcount, n);
                base = __shfl_sync(FULLMASK, base, leader);
                if (pos) {
                    int off = __popc(pm & ((1u << lane) - 1u));
                    g_plist[base + off] = (row << 8) | (unsigned int)lbl;
                }
                double dlt = (double)lt;
                #pragma unroll
                for (int o = 16; o; o >>= 1) dlt += __shfl_xor_sync(FULLMASK, dlt, o);
                if (lane == leader) {
                    atomicAdd(&g_loc, dlt);
                    atomicAdd(&g_numpos[b], n);
                }
            }
            if (valid) g_match[row] = pos ? (unsigned char)bt : (unsigned char)0xFF;
        }
    }
}

// ---------------------------------------------------------------------------
// Kernel 2: scatter fixup — row p = best_prior[b][t] becomes positive with
// truth t (last t wins among duplicates) iff its best overlap <= 0.5.
// Marks g_match so k_select's positive mask covers these rows.
// ---------------------------------------------------------------------------
__global__ void k_fix(const float* __restrict__ loc_pred,
                      const float* __restrict__ targets,
                      const float* __restrict__ anchors) {
    const int b = blockIdx.x;
    const int t = threadIdx.x;
    if (t >= TT) return;
    unsigned long long pk = g_bp[b * TT + t];
    const int p = (int)(~(unsigned int)(pk & 0xFFFFFFFFull));
    unsigned int peers = __match_any_sync(0x00FFFFFFu, p);
    if (t != 31 - __clz(peers)) return;          // last t wins
    const unsigned int row = (unsigned int)(b * PP + p);
    if (g_match[row] != 0xFF) return;            // bt-match already positive
    g_match[row] = (unsigned char)t;             // mark positive for k_select mask

    const float* tr = targets + ((size_t)b * TT + t) * 5;
    float x0 = tr[0], y0 = tr[1], x1 = tr[2], y1 = tr[3];
    int lbl = (int)tr[4];
    int idx = atomicAdd(&g_pcount, 1);
    g_plist[idx] = (row << 8) | (unsigned int)lbl;

    float4 a = ((const float4*)anchors)[p];
    float4 lp = ((const float4*)loc_pred)[row];
    float e0 = ((x0 + x1) * 0.5f - a.x) / a.z;
    float e1 = ((y0 + y1) * 0.5f - a.y) / a.w;
    float e2 = __logf(x1 - x0) - __logf(a.z);
    float e3 = __logf(y1 - y0) - __logf(a.w);
    float d, ad, lt = 0.f;
    d = lp.x - e0; ad = fabsf(d); lt += (ad < 1.f) ? 0.5f * d * d : ad - 0.5f;
    d = lp.y - e1; ad = fabsf(d); lt += (ad < 1.f) ? 0.5f * d * d : ad - 0.5f;
    d = lp.z - e2; ad = fabsf(d); lt += (ad < 1.f) ? 0.5f * d * d : ad - 0.5f;
    d = lp.w - e3; ad = fabsf(d); lt += (ad < 1.f) ? 0.5f * d * d : ad - 0.5f;
    atomicAdd(&g_loc, (double)lt);
    atomicAdd(&g_numpos[b], 1);
}

// ---------------------------------------------------------------------------
// Kernel 3: k_select v2 — parallel suffix-scan radix select + folded positive
// gather (was k_zero). The old tid-0 256-bin scan (4 x ~9k serial cycles) is
// replaced by a 256-thread warp-shuffle suffix scan (~200 cycles).
// ---------------------------------------------------------------------------
__global__ void __launch_bounds__(1024) k_select(const float* __restrict__ conf_pred) {
    __shared__ int hist[256];
    __shared__ int wtot[8];
    __shared__ unsigned int s_sel;
    __shared__ int s_r;
    __shared__ double s_sum;
    __shared__ int s_cnt;

    const int b = blockIdx.x;
    const int tid = threadIdx.x;
    const int lane = tid & 31;

    // ---- folded k_zero: positive poscls gather over plist slice ----
    {
        const int n = g_pcount;
        double acc = 0.0;
        for (int i = b * 1024 + tid; i < n; i += BB * 1024) {
            unsigned int e = g_plist[i];
            size_t row = (size_t)(e >> 8);
            int lbl = (int)(e & 255u);
            const float* cp = conf_pred + row * CC;
            acc += (double)(g_closs[row] + __ldg(cp) - __ldg(cp + lbl));
        }
        #pragma unroll
        for (int o = 16; o; o >>= 1) acc += __shfl_xor_sync(FULLMASK, acc, o);
        if (lane == 0 && acc != 0.0) atomicAdd(&g_poscls, acc);
    }

    const int np = g_numpos[b];
    long long Kl = 3LL * np;
    if (Kl > PP - 1) Kl = PP - 1;
    const int K = (int)Kl;
    if (K <= 0) {
        if (tid == 0) atomicAdd(&g_nsel, np);
        return;
    }
    const float* cl = g_closs + (size_t)b * PP;
    const unsigned char* gm = g_match + (size_t)b * PP;

    // Padding/positives -> 0u (=0.0f): bin 0; selection never descends there
    // (K-th largest closs > 0: every negative has lse > c0).
    unsigned int v[24];
    #pragma unroll
    for (int i = 0; i < 24; i++) {
        int idx = tid + i * 1024;
        bool neg = (idx < PP) && (gm[idx] == 0xFF);
        v[i] = neg ? __float_as_uint(cl[idx]) : 0u;
    }

    if (tid < 256) hist[tid] = 0;
    if (tid == 0) { s_sum = 0.0; s_cnt = 0; }
    __syncthreads();

    unsigned int prefix = 0, pmask = 0;
    int r = K;
    #pragma unroll
    for (int shift = 24; shift >= 0; shift -= 8) {
        // --- build histogram (warp-aggregated atomics) ---
        #pragma unroll
        for (int i = 0; i < 24; i++) {
            unsigned int u = v[i];
            bool act = ((u & pmask) == prefix);
            unsigned int bal = __ballot_sync(FULLMASK, act);
            if (act) {
                unsigned int bin = (u >> shift) & 255u;
                unsigned int peers = __match_any_sync(bal, bin);
                if (lane == __ffs(peers) - 1)
                    atomicAdd(&hist[bin], __popc(peers));
            }
        }
        __syncthreads();

        // --- parallel suffix scan over 256 bins ---
        int h = 0, x = 0;
        if (tid < 256) {
            h = hist[tid];
            x = h;
            #pragma unroll
            for (int o = 1; o < 32; o <<= 1) {
                int y = __shfl_down_sync(FULLMASK, x, o);
                if (lane + o < 32) x += y;       // x = sum hist[tid .. warp-end]
            }
            if (lane == 0) wtot[tid >> 5] = x;   // warp-group total
            hist[tid] = 0;                       // clear for next pass
        }
        __syncthreads();
        if (tid < 256) {
            const int wi = tid >> 5;
            int add = 0;
            #pragma unroll
            for (int wj = 0; wj < 8; wj++)
                if (wj > wi) add += wtot[wj];
            int sfx = x + add;                   // suffix sum from bin tid
            // unique bin: sfx >= r > sfx - h  (h=0 bins can't satisfy)
            if (sfx >= r && sfx - h < r) { s_sel = (unsigned int)tid; s_r = r - (sfx - h); }
        }
        __syncthreads();
        prefix |= s_sel << shift;
        pmask |= 0xFFu << shift;
        r = s_r;
    }
    const float theta = __uint_as_float(prefix);   // exact K-th largest

    double sum = 0.0; int cnt = 0;
    #pragma unroll
    for (int i = 0; i < 24; i++) {
        float f = __uint_as_float(v[i]);
        if (f > theta) { sum += (double)f; cnt++; }
    }
    #pragma unroll
    for (int o = 16; o; o >>= 1) {
        sum += __shfl_xor_sync(FULLMASK, sum, o);
        cnt += __shfl_xor_sync(FULLMASK, cnt, o);
    }
    if (lane == 0) { atomicAdd(&s_sum, sum); atomicAdd(&s_cnt, cnt); }
    __syncthreads();
    if (tid == 0) {
        double negsum = s_sum + (double)(K - s_cnt) * (double)theta;
        atomicAdd(&g_negcls, negsum);
        atomicAdd(&g_nsel, np + K);
    }
}

// ---------------------------------------------------------------------------
// Kernel 4: combine (non-selected rows each contribute exactly log C).
// ---------------------------------------------------------------------------
__global__ void k_final(float* out) {
    const int t = threadIdx.x;           // 64 threads
    int np = (t < BB) ? g_numpos[t] : 0;
    #pragma unroll
    for (int o = 16; o; o >>= 1) np += __shfl_xor_sync(FULLMASK, np, o);
    __shared__ int s_np[2];
    if ((t & 31) == 0) s_np[t >> 5] = np;
    __syncthreads();
    if (t == 0) {
        double N = (double)(s_np[0] + s_np[1]);
        double cls = g_poscls + g_negcls +
                     (double)((long long)BB * PP - (long long)g_nsel) * log((double)CC);
        out[0] = (float)(g_loc / N);
        out[1] = (float)(cls / N);
    }
}

// ---------------------------------------------------------------------------
// Launch
// ---------------------------------------------------------------------------
extern "C" void kernel_launch(void* const* d_in, const int* in_sizes, int n_in,
                              void* d_out, int out_size) {
    const float *loc = nullptr, *conf = nullptr, *tgt = nullptr, *anc = nullptr;
    for (int i = 0; i < n_in; i++) {
        long long s = in_sizes[i];
        if (s == (long long)BB * PP * 4)       loc  = (const float*)d_in[i];
        else if (s == (long long)BB * PP * CC) conf = (const float*)d_in[i];
        else if (s == (long long)BB * TT * 5)  tgt  = (const float*)d_in[i];
        else if (s == (long long)PP * 4)       anc  = (const float*)d_in[i];
    }
    float* out = (float*)d_out;

    k_init<<<(BB * TT + 255) / 256, 256>>>();                 // 1
    k_fused<<<NBLK, 128, FUSED_SMEM>>>(conf, loc, tgt, anc);  // 2 (2:2 split)
    k_fix<<<BB, 32>>>(loc, tgt, anc);                         // 3
    k_select<<<BB, 1024>>>(conf);                             // 4 <- profiled
    k_final<<<1, 64>>>(out);                                  // 5
}